// round 12
// baseline (speedup 1.0000x reference)
#include <cuda_runtime.h>
#include <cuda_bf16.h>

#define MAXN 50000
#define MAXE 800000
#define NGRAPH 128
#define SCAN_CHUNK 2048

typedef unsigned long long u64;

// Scratch (device globals; zero-initialized at module load).
// Invariant at entry: g_deg, g_EA, g_sc are zero; k_final restores them
// (deg is restored by k_scan2).
__device__ float          g_h[MAXN * 64];
__device__ __nv_bfloat16  g_t[MAXN * 64];
__device__ float          g_pre[MAXN * 64];
__device__ float          g_EA[MAXN * 12];
__device__ int            g_deg[MAXN];
__device__ int            g_off[MAXN + 1];
__device__ int            g_cur[MAXN];
__device__ int            g_csr[MAXE];
__device__ int            g_bsum[64];
__device__ float          g_sc[2 * NGRAPH];

__device__ __forceinline__ float lrelu(float a) { return a > 0.0f ? a : 0.01f * a; }

__device__ __forceinline__ void fma2(u64& d, u64 a, u64 b) {
    asm("fma.rn.f32x2 %0, %1, %2, %0;" : "+l"(d) : "l"(a), "l"(b));
}
__device__ __forceinline__ u64 pack2(float a) {
    u64 r; unsigned int ai = __float_as_uint(a);
    asm("mov.b64 %0, {%1, %1};" : "=l"(r) : "r"(ai));
    return r;
}
__device__ __forceinline__ unsigned int bf2_from_u64(u64 p) {
    unsigned int lo, hi, r;
    asm("mov.b64 {%0, %1}, %2;" : "=r"(lo), "=r"(hi) : "l"(p));
    asm("cvt.rn.bf16x2.f32 %0, %1, %2;" : "=r"(r)
        : "f"(__uint_as_float(hi)), "f"(__uint_as_float(lo)));
    return r;
}
__device__ __forceinline__ void red_add_v4(float* addr, float4 v) {
    asm volatile("red.global.add.v4.f32 [%0], {%1,%2,%3,%4};"
                 :: "l"(addr), "f"(v.x), "f"(v.y), "f"(v.z), "f"(v.w) : "memory");
}

// ---------------------------------------------------------------------------
// Edge pass: deg histogram + EA = segment_sum(edge_attr, dst), fused.
// ---------------------------------------------------------------------------
__global__ void k_edge(const int* __restrict__ ei, const float* __restrict__ edge_attr,
                       int* __restrict__ deg, float* __restrict__ EA, int E) {
    int e = blockIdx.x * 256 + threadIdx.x;
    if (e >= E) return;
    int dst = ei[E + e];
    atomicAdd(&deg[dst], 1);
    const float4* a4 = (const float4*)(edge_attr + (size_t)e * 12);
    float4 v0 = a4[0], v1 = a4[1], v2 = a4[2];
    float* base = EA + dst * 12;
    red_add_v4(base, v0);
    red_add_v4(base + 4, v1);
    red_add_v4(base + 8, v2);
}

// ---------------------------------------------------------------------------
// Parallel exclusive scan of deg -> off/cur; scan2 restores deg=0.
// ---------------------------------------------------------------------------
__global__ void k_scan1(const int* __restrict__ deg, int* __restrict__ bsum, int N) {
    __shared__ int ws[8];
    int bid = blockIdx.x, tid = threadIdx.x;
    int base = bid * SCAN_CHUNK + tid * 8;
    int s = 0;
#pragma unroll
    for (int i = 0; i < 8; i++) {
        int idx = base + i;
        s += (idx < N) ? deg[idx] : 0;
    }
#pragma unroll
    for (int o = 16; o > 0; o >>= 1) s += __shfl_down_sync(0xffffffffu, s, o);
    if ((tid & 31) == 0) ws[tid >> 5] = s;
    __syncthreads();
    if (tid == 0) {
        int t = 0;
#pragma unroll
        for (int i = 0; i < 8; i++) t += ws[i];
        bsum[bid] = t;
    }
}

__global__ void k_scan2(int* __restrict__ deg, const int* __restrict__ bsum,
                        int* __restrict__ off, int* __restrict__ cur, int N, int E) {
    __shared__ int ws[8];
    __shared__ int sprefix;
    int bid = blockIdx.x, tid = threadIdx.x;
    if (tid == 0) {
        int p = 0;
        for (int i = 0; i < bid; i++) p += bsum[i];
        sprefix = p;
        if (bid == 0) off[N] = E;
    }
    int base = bid * SCAN_CHUNK + tid * 8;
    int v[8]; int s = 0;
#pragma unroll
    for (int i = 0; i < 8; i++) {
        int idx = base + i;
        v[i] = (idx < N) ? deg[idx] : 0;
        s += v[i];
    }
    int lane = tid & 31, wid = tid >> 5;
    int inc = s;
#pragma unroll
    for (int o = 1; o < 32; o <<= 1) {
        int t = __shfl_up_sync(0xffffffffu, inc, o);
        if (lane >= o) inc += t;
    }
    if (lane == 31) ws[wid] = inc;
    __syncthreads();
    if (tid == 0) {
        int run = 0;
#pragma unroll
        for (int i = 0; i < 8; i++) { int t = ws[i]; ws[i] = run; run += t; }
    }
    __syncthreads();
    int ex = sprefix + ws[wid] + inc - s;
#pragma unroll
    for (int i = 0; i < 8; i++) {
        int idx = base + i;
        if (idx < N) { off[idx] = ex; cur[idx] = ex; deg[idx] = 0; }
        ex += v[i];
    }
}

__global__ void k_fill(const int* __restrict__ ei, int* __restrict__ cur,
                       int* __restrict__ csr, int E) {
    int e = blockIdx.x * 256 + threadIdx.x;
    if (e >= E) return;
    int src = ei[e];
    int dst = ei[E + e];
    int pos = atomicAdd(&cur[dst], 1);
    csr[pos] = src;
}

// ---------------------------------------------------------------------------
// Fused layer GEMM. Tile: 64 nodes x 128 outputs (64 t-ch | 64 pre-ch).
// ---------------------------------------------------------------------------
#define OFF_X   0
#define OFF_W   4352
#define OFF_B   12544
#define OFF_WIN 12608
#define OFF_BIN 13376
#define SMEM_FLOATS 13440

template<bool FIRST>
__global__ void __launch_bounds__(256, 3)
k_gemm(const float* __restrict__ state, const float* __restrict__ action,
       const float* __restrict__ Win, const float* __restrict__ bin,
       const float* __restrict__ h,
       const float* __restrict__ Wn, const float* __restrict__ Wsf,
       const float* __restrict__ bias,
       __nv_bfloat16* __restrict__ t, float* __restrict__ pre, int N) {
    extern __shared__ float sm[];
    int tid = threadIdx.x;
    int base = blockIdx.x * 64;

    if (!FIRST) {
        for (int j = tid; j < 1024; j += 256) {
            int node = j >> 4, kq = j & 15;
            int gn = base + node;
            float4 v = make_float4(0.f, 0.f, 0.f, 0.f);
            if (gn < N) v = ((const float4*)h)[gn * 16 + kq];
            *(float4*)&sm[OFF_X + node * 68 + kq * 4] = v;
        }
    } else {
        for (int j = tid; j < 768; j += 256) sm[OFF_WIN + j] = Win[j];
        if (tid < 64) sm[OFF_BIN + tid] = bin[tid];
    }
    for (int j = tid; j < 2048; j += 256) {
        int k = j >> 5, c4 = j & 31;
        float4 wv = (c4 < 16) ? ((const float4*)Wn)[k * 16 + c4]
                              : ((const float4*)Wsf)[k * 16 + (c4 - 16)];
        *(float4*)&sm[OFF_W + k * 128 + c4 * 4] = wv;
    }
    if (tid < 64) sm[OFF_B + tid] = bias[tid];
    __syncthreads();

    if (FIRST) {
        int node = tid & 63, q = tid >> 6;
        int gn = base + node;
        float xin[12];
#pragma unroll
        for (int k = 0; k < 12; k++) xin[k] = 0.0f;
        if (gn < N) {
#pragma unroll
            for (int k = 0; k < 8; k++) xin[k] = state[gn * 8 + k];
#pragma unroll
            for (int k = 0; k < 4; k++) xin[8 + k] = action[gn * 4 + k];
        }
        int c0 = q * 16;
#pragma unroll 4
        for (int c = c0; c < c0 + 16; c++) {
            float a = sm[OFF_BIN + c];
#pragma unroll
            for (int k = 0; k < 12; k++) a += xin[k] * sm[OFF_WIN + k * 64 + c];
            sm[OFF_X + node * 68 + c] = lrelu(a);
        }
        __syncthreads();
    }

    int ty = tid >> 4;
    int tx = tid & 15;
    bool isPre = tx >= 8;
    int cb = (tx & 7) * 8;

    u64 acc[4][4];
    if (isPre) {
        const u64* b2 = (const u64*)&sm[OFF_B + cb];
#pragma unroll
        for (int n = 0; n < 4; n++) {
            acc[n][0] = b2[0]; acc[n][1] = b2[1];
            acc[n][2] = b2[2]; acc[n][3] = b2[3];
        }
    } else {
#pragma unroll
        for (int n = 0; n < 4; n++)
#pragma unroll
            for (int q = 0; q < 4; q++) acc[n][q] = 0ull;
    }

    const float* xrow  = &sm[OFF_X + ty * 4 * 68];
    const float* wbase = &sm[OFF_W + (isPre ? 64 : 0) + cb];

#pragma unroll 4
    for (int k = 0; k < 64; k++) {
        const ulonglong2* w2 = (const ulonglong2*)(wbase + k * 128);
        ulonglong2 wa = w2[0], wb = w2[1];
#pragma unroll
        for (int n = 0; n < 4; n++) {
            u64 a = pack2(xrow[n * 68 + k]);
            fma2(acc[n][0], a, wa.x); fma2(acc[n][1], a, wa.y);
            fma2(acc[n][2], a, wb.x); fma2(acc[n][3], a, wb.y);
        }
    }

    if (isPre) {
#pragma unroll
        for (int n = 0; n < 4; n++) {
            int gn = base + ty * 4 + n;
            if (gn < N) {
                ulonglong2* o = (ulonglong2*)(pre + gn * 64 + cb);
                o[0] = make_ulonglong2(acc[n][0], acc[n][1]);
                o[1] = make_ulonglong2(acc[n][2], acc[n][3]);
            }
        }
    } else {
#pragma unroll
        for (int n = 0; n < 4; n++) {
            int gn = base + ty * 4 + n;
            if (gn < N) {
                uint4 o;
                o.x = bf2_from_u64(acc[n][0]);
                o.y = bf2_from_u64(acc[n][1]);
                o.z = bf2_from_u64(acc[n][2]);
                o.w = bf2_from_u64(acc[n][3]);
                *(uint4*)(t + gn * 64 + cb) = o;
            }
        }
    }
}

// ---------------------------------------------------------------------------
// CSR pull, warp per node, lane owns 2 channels.
//   s = pre[n] + EA[n]@We + sum_{src in in(n)} t[src]   (t is bf16x2)
// All neighbors processed in 16-wide masked batches (MLP=16, no serial tail).
// Invalid slots load t2[lane] (index 0, harmless) and are masked to zero.
// ---------------------------------------------------------------------------
template<bool FINAL>
__global__ void k_pull(const int* __restrict__ off, const int* __restrict__ csr,
                       const __nv_bfloat16* __restrict__ t, const float* __restrict__ pre,
                       const float* __restrict__ EA, const float* __restrict__ We,
                       float* __restrict__ hout, const int* __restrict__ batch,
                       const float* __restrict__ Wout, const float* __restrict__ bout,
                       float* __restrict__ sc, int N) {
    __shared__ float Wes[768];
    int tid = threadIdx.x;
    for (int i = tid; i < 768; i += 256) Wes[i] = We[i];
    __syncthreads();

    int node = (blockIdx.x * 256 + tid) >> 5;
    int lane = tid & 31;
    if (node >= N) return;
    int s = off[node], e = off[node + 1];
    const __nv_bfloat162* t2 = (const __nv_bfloat162*)t;
    float2 p = ((const float2*)pre)[node * 32 + lane];
    float ax = p.x, ay = p.y;

    float eav = (lane < 12) ? EA[node * 12 + lane] : 0.0f;
    const float2* We2 = (const float2*)Wes;
#pragma unroll
    for (int k = 0; k < 12; k++) {
        float a = __shfl_sync(0xffffffffu, eav, k);
        float2 w = We2[k * 32 + lane];
        ax += a * w.x; ay += a * w.y;
    }

    for (int j = s; j < e; j += 32) {
        int cnt = min(32, e - j);
        int sv = (j + lane < e) ? csr[j + lane] : 0;
#pragma unroll 1
        for (int i = 0; i < cnt; i += 16) {
            float2 v[16];
#pragma unroll
            for (int k = 0; k < 16; k++) {
                int b = __shfl_sync(0xffffffffu, sv, i + k);
                v[k] = __bfloat1622float2(t2[b * 32 + lane]);
            }
            int rem = cnt - i;
            if (rem >= 16) {
#pragma unroll
                for (int k = 0; k < 16; k += 4) {
                    ax += ((v[k].x + v[k+1].x) + (v[k+2].x + v[k+3].x));
                    ay += ((v[k].y + v[k+1].y) + (v[k+2].y + v[k+3].y));
                }
            } else {
#pragma unroll
                for (int k = 0; k < 16; k++) {
                    float m = (k < rem) ? 1.0f : 0.0f;
                    ax += v[k].x * m;
                    ay += v[k].y * m;
                }
            }
        }
    }

    float h0 = lrelu(ax), h1 = lrelu(ay);
    if (!FINAL) {
        ((float2*)hout)[node * 32 + lane] = make_float2(h0, h1);
    } else {
        float p2 = h0 * __ldg(&Wout[2 * lane]) + h1 * __ldg(&Wout[2 * lane + 1]);
#pragma unroll
        for (int o = 16; o > 0; o >>= 1) p2 += __shfl_down_sync(0xffffffffu, p2, o);
        if (lane == 0) {
            int b = batch[node];
            atomicAdd(&sc[b], p2 + bout[0]);
            atomicAdd(&sc[NGRAPH + b], 1.0f);
        }
    }
}

// ---------------------------------------------------------------------------
// Final: out = sums/max(counts,1); restore zero-invariant on EA/sc.
// ---------------------------------------------------------------------------
__global__ void k_final(float* __restrict__ sc, float* __restrict__ out,
                        float* __restrict__ EA, int G, int N) {
    int gid = blockIdx.x * 256 + threadIdx.x;
    int tot4 = (N * 12) >> 2;
    if (gid < tot4) ((float4*)EA)[gid] = make_float4(0.f, 0.f, 0.f, 0.f);
    if (blockIdx.x == 0 && threadIdx.x < G) {
        float sv = sc[threadIdx.x], cv = sc[NGRAPH + threadIdx.x];
        out[threadIdx.x] = sv / fmaxf(cv, 1.0f);
        sc[threadIdx.x] = 0.0f;
        sc[NGRAPH + threadIdx.x] = 0.0f;
    }
}

// ---------------------------------------------------------------------------
extern "C" void kernel_launch(void* const* d_in, const int* in_sizes, int n_in,
                              void* d_out, int out_size) {
    const float* state     = (const float*)d_in[0];
    const float* action    = (const float*)d_in[1];
    const int*   edge_idx  = (const int*)d_in[2];
    const float* edge_attr = (const float*)d_in[3];
    const int*   batch     = (const int*)d_in[4];
    const float* W_in      = (const float*)d_in[5];
    const float* b_in      = (const float*)d_in[6];
    const float* W_self    = (const float*)d_in[7];
    const float* W_nbr     = (const float*)d_in[8];
    const float* W_edge    = (const float*)d_in[9];
    const float* b_conv    = (const float*)d_in[10];
    const float* W_out     = (const float*)d_in[11];
    const float* b_out     = (const float*)d_in[12];
    float* out = (float*)d_out;

    const int N = in_sizes[0] / 8;
    const int E = in_sizes[3] / 12;
    const int G = out_size;

    float *h_p, *pre_p, *ea_p, *sc_p;
    __nv_bfloat16* t_p;
    int *deg_p, *off_p, *cur_p, *csr_p, *bsum_p;
    cudaGetSymbolAddress((void**)&h_p,    g_h);
    cudaGetSymbolAddress((void**)&t_p,    g_t);
    cudaGetSymbolAddress((void**)&pre_p,  g_pre);
    cudaGetSymbolAddress((void**)&ea_p,   g_EA);
    cudaGetSymbolAddress((void**)&deg_p,  g_deg);
    cudaGetSymbolAddress((void**)&off_p,  g_off);
    cudaGetSymbolAddress((void**)&cur_p,  g_cur);
    cudaGetSymbolAddress((void**)&csr_p,  g_csr);
    cudaGetSymbolAddress((void**)&bsum_p, g_bsum);
    cudaGetSymbolAddress((void**)&sc_p,   g_sc);

    const int smemBytes = SMEM_FLOATS * 4;
    cudaFuncSetAttribute(k_gemm<true>,  cudaFuncAttributeMaxDynamicSharedMemorySize, smemBytes);
    cudaFuncSetAttribute(k_gemm<false>, cudaFuncAttributeMaxDynamicSharedMemorySize, smemBytes);

    static cudaStream_t sA = nullptr;
    static cudaEvent_t evRoot = nullptr, evCsr = nullptr;
    if (!sA) {
        cudaStreamCreateWithFlags(&sA, cudaStreamNonBlocking);
        cudaEventCreateWithFlags(&evRoot, cudaEventDisableTiming);
        cudaEventCreateWithFlags(&evCsr,  cudaEventDisableTiming);
    }

    const int pullBlocks = (N + 7) / 8;
    const int gemmBlocks = (N + 63) / 64;
    const int edgeBlocks = (E + 255) / 256;
    const int scanBlocks = (N + SCAN_CHUNK - 1) / SCAN_CHUNK;
    const int finBlocks  = ((N * 12) / 4 + 255) / 256;

    // fork: CSR/EA chain on side stream (enqueue order puts gemm0 4th so
    // ncu's fixed capture slot lands on the GEMM this round)
    cudaEventRecord(evRoot, 0);
    cudaStreamWaitEvent(sA, evRoot, 0);
    k_edge<<<edgeBlocks, 256, 0, sA>>>(edge_idx, edge_attr, deg_p, ea_p, E);       // #1
    k_scan1<<<scanBlocks, 256, 0, sA>>>(deg_p, bsum_p, N);                          // #2
    k_scan2<<<scanBlocks, 256, 0, sA>>>(deg_p, bsum_p, off_p, cur_p, N, E);         // #3

    // main chain: gemm0 starts immediately (no edge dependency)
    k_gemm<true><<<gemmBlocks, 256, smemBytes>>>(state, action, W_in, b_in,         // #4
                                                 nullptr, W_nbr, W_self, b_conv,
                                                 t_p, pre_p, N);

    k_fill<<<edgeBlocks, 256, 0, sA>>>(edge_idx, cur_p, csr_p, E);                  // #5
    cudaEventRecord(evCsr, sA);

    cudaStreamWaitEvent(0, evCsr, 0);
    k_pull<false><<<pullBlocks, 256>>>(off_p, csr_p, t_p, pre_p, ea_p, W_edge,      // #6
                                       h_p, nullptr, nullptr, nullptr, nullptr, N);
    k_gemm<false><<<gemmBlocks, 256, smemBytes>>>(nullptr, nullptr, nullptr, nullptr, // #7
                                                  h_p, W_nbr + 4096, W_self + 4096,
                                                  b_conv + 64, t_p, pre_p, N);
    k_pull<true><<<pullBlocks, 256>>>(off_p, csr_p, t_p, pre_p, ea_p, W_edge + 768, // #8
                                      nullptr, batch, W_out, b_out, sc_p, N);
    k_final<<<finBlocks, 256>>>(sc_p, out, ea_p, G, N);                             // #9
}

// round 13
// speedup vs baseline: 1.0981x; 1.0981x over previous
#include <cuda_runtime.h>
#include <cuda_bf16.h>
#include <mma.h>

using namespace nvcuda;

#define MAXN 50000
#define MAXE 800000
#define NGRAPH 128
#define SCAN_CHUNK 2048

typedef unsigned long long u64;

// Scratch (device globals; zero-initialized at module load).
// Invariant at entry: g_deg, g_EA, g_sc are zero (deg restored by k_scan2,
// EA/sc restored by k_final).
__device__ float          g_h[MAXN * 64];
__device__ __nv_bfloat16  g_t[MAXN * 64];
__device__ float          g_pre[MAXN * 64];
__device__ float          g_EA[MAXN * 12];
__device__ int            g_deg[MAXN];
__device__ int            g_off[MAXN + 1];
__device__ int            g_cur[MAXN];
__device__ int            g_csr[MAXE];
__device__ int            g_bsum[64];
__device__ float          g_sc[2 * NGRAPH];

__device__ __forceinline__ float lrelu(float a) { return a > 0.0f ? a : 0.01f * a; }

__device__ __forceinline__ unsigned int bf2pair(float lo, float hi) {
    unsigned int r;
    asm("cvt.rn.bf16x2.f32 %0, %1, %2;" : "=r"(r) : "f"(hi), "f"(lo));
    return r;
}
__device__ __forceinline__ void red_add_v4(float* addr, float4 v) {
    asm volatile("red.global.add.v4.f32 [%0], {%1,%2,%3,%4};"
                 :: "l"(addr), "f"(v.x), "f"(v.y), "f"(v.z), "f"(v.w) : "memory");
}

// ---------------------------------------------------------------------------
// Edge pass: deg histogram + EA = segment_sum(edge_attr, dst), fused.
// ---------------------------------------------------------------------------
__global__ void k_edge(const int* __restrict__ ei, const float* __restrict__ edge_attr,
                       int* __restrict__ deg, float* __restrict__ EA, int E) {
    int e = blockIdx.x * 256 + threadIdx.x;
    if (e >= E) return;
    int dst = ei[E + e];
    atomicAdd(&deg[dst], 1);
    const float4* a4 = (const float4*)(edge_attr + (size_t)e * 12);
    float4 v0 = a4[0], v1 = a4[1], v2 = a4[2];
    float* base = EA + dst * 12;
    red_add_v4(base, v0);
    red_add_v4(base + 4, v1);
    red_add_v4(base + 8, v2);
}

// ---------------------------------------------------------------------------
// Parallel exclusive scan of deg -> off/cur; scan2 restores deg=0.
// ---------------------------------------------------------------------------
__global__ void k_scan1(const int* __restrict__ deg, int* __restrict__ bsum, int N) {
    __shared__ int ws[8];
    int bid = blockIdx.x, tid = threadIdx.x;
    int base = bid * SCAN_CHUNK + tid * 8;
    int s = 0;
#pragma unroll
    for (int i = 0; i < 8; i++) {
        int idx = base + i;
        s += (idx < N) ? deg[idx] : 0;
    }
#pragma unroll
    for (int o = 16; o > 0; o >>= 1) s += __shfl_down_sync(0xffffffffu, s, o);
    if ((tid & 31) == 0) ws[tid >> 5] = s;
    __syncthreads();
    if (tid == 0) {
        int t = 0;
#pragma unroll
        for (int i = 0; i < 8; i++) t += ws[i];
        bsum[bid] = t;
    }
}

__global__ void k_scan2(int* __restrict__ deg, const int* __restrict__ bsum,
                        int* __restrict__ off, int* __restrict__ cur, int N, int E) {
    __shared__ int ws[8];
    __shared__ int sprefix;
    int bid = blockIdx.x, tid = threadIdx.x;
    if (tid == 0) {
        int p = 0;
        for (int i = 0; i < bid; i++) p += bsum[i];
        sprefix = p;
        if (bid == 0) off[N] = E;
    }
    int base = bid * SCAN_CHUNK + tid * 8;
    int v[8]; int s = 0;
#pragma unroll
    for (int i = 0; i < 8; i++) {
        int idx = base + i;
        v[i] = (idx < N) ? deg[idx] : 0;
        s += v[i];
    }
    int lane = tid & 31, wid = tid >> 5;
    int inc = s;
#pragma unroll
    for (int o = 1; o < 32; o <<= 1) {
        int t = __shfl_up_sync(0xffffffffu, inc, o);
        if (lane >= o) inc += t;
    }
    if (lane == 31) ws[wid] = inc;
    __syncthreads();
    if (tid == 0) {
        int run = 0;
#pragma unroll
        for (int i = 0; i < 8; i++) { int t = ws[i]; ws[i] = run; run += t; }
    }
    __syncthreads();
    int ex = sprefix + ws[wid] + inc - s;
#pragma unroll
    for (int i = 0; i < 8; i++) {
        int idx = base + i;
        if (idx < N) { off[idx] = ex; cur[idx] = ex; deg[idx] = 0; }
        ex += v[i];
    }
}

__global__ void k_fill(const int* __restrict__ ei, int* __restrict__ cur,
                       int* __restrict__ csr, int E) {
    int e = blockIdx.x * 256 + threadIdx.x;
    if (e >= E) return;
    int src = ei[e];
    int dst = ei[E + e];
    int pos = atomicAdd(&cur[dst], 1);
    csr[pos] = src;
}

// ---------------------------------------------------------------------------
// Fused layer GEMM on TENSOR CORES (WMMA tf32 m16n16k8).
// Tile: 64 nodes x 128 outputs (64 t-ch | 64 pre-ch).
//   X = FIRST ? lrelu([state|action]@W_in + b_in) (in-loader) : h (global)
//   t   = X @ W_nbr (bf16x2);  pre = X @ W_self + b_conv (fp32)
// Warp w: node strip (w&3)*16, channel half (w>>2); 4 C tiles of 16x16.
// Epilogue stages C via smem (X/W region reused after sync).
// ---------------------------------------------------------------------------
#define XS      72                    // X row stride (288B, 32B-aligned rows)
#define OFF_X   0                     // 64*72 = 4608
#define OFF_W   4608                  // 64*128 = 8192 -> 12800
#define OFF_B   12800                 // 64
#define OFF_WIN 12864                 // 768
#define OFF_BIN 13632                 // 64
#define SMEM_FLOATS 13696             // 54,784 B

template<bool FIRST>
__global__ void __launch_bounds__(256, 3)
k_gemm(const float* __restrict__ state, const float* __restrict__ action,
       const float* __restrict__ Win, const float* __restrict__ bin,
       const float* __restrict__ h,
       const float* __restrict__ Wn, const float* __restrict__ Wsf,
       const float* __restrict__ bias,
       __nv_bfloat16* __restrict__ t, float* __restrict__ pre, int N) {
    extern __shared__ float sm[];
    int tid = threadIdx.x;
    int base = blockIdx.x * 64;

    // ---- stage X (or W_in) + weights ----
    if (!FIRST) {
        for (int j = tid; j < 1024; j += 256) {
            int node = j >> 4, kq = j & 15;
            int gn = base + node;
            float4 v = make_float4(0.f, 0.f, 0.f, 0.f);
            if (gn < N) v = ((const float4*)h)[gn * 16 + kq];
            *(float4*)&sm[OFF_X + node * XS + kq * 4] = v;
        }
    } else {
        for (int j = tid; j < 768; j += 256) sm[OFF_WIN + j] = Win[j];
        if (tid < 64) sm[OFF_BIN + tid] = bin[tid];
    }
    for (int j = tid; j < 2048; j += 256) {
        int k = j >> 5, c4 = j & 31;
        float4 wv = (c4 < 16) ? ((const float4*)Wn)[k * 16 + c4]
                              : ((const float4*)Wsf)[k * 16 + (c4 - 16)];
        *(float4*)&sm[OFF_W + k * 128 + c4 * 4] = wv;
    }
    if (tid < 64) sm[OFF_B + tid] = bias[tid];
    __syncthreads();

    // ---- FIRST: X = lrelu([s|a]@W_in + b_in) ----
    if (FIRST) {
        int node = tid & 63, q = tid >> 6;
        int gn = base + node;
        float xin[12];
#pragma unroll
        for (int k = 0; k < 12; k++) xin[k] = 0.0f;
        if (gn < N) {
#pragma unroll
            for (int k = 0; k < 8; k++) xin[k] = state[gn * 8 + k];
#pragma unroll
            for (int k = 0; k < 4; k++) xin[8 + k] = action[gn * 4 + k];
        }
        int c0 = q * 16;
#pragma unroll 4
        for (int c = c0; c < c0 + 16; c++) {
            float a = sm[OFF_BIN + c];
#pragma unroll
            for (int k = 0; k < 12; k++) a += xin[k] * sm[OFF_WIN + k * 64 + c];
            sm[OFF_X + node * XS + c] = lrelu(a);
        }
        __syncthreads();
    }

    // ---- tensor-core GEMM ----
    int warp = tid >> 5;
    int strip = warp & 3;       // 16-node strip
    int chalf = warp >> 2;      // 0 = t channels, 1 = pre channels

    wmma::fragment<wmma::accumulator, 16, 16, 8, float> c[4];
#pragma unroll
    for (int j = 0; j < 4; j++) wmma::fill_fragment(c[j], 0.0f);

#pragma unroll
    for (int kk = 0; kk < 64; kk += 8) {
        wmma::fragment<wmma::matrix_a, 16, 16, 8, wmma::precision::tf32, wmma::row_major> a;
        wmma::load_matrix_sync(a, &sm[OFF_X + strip * 16 * XS + kk], XS);
#pragma unroll
        for (int i = 0; i < a.num_elements; i++) a.x[i] = wmma::__float_to_tf32(a.x[i]);
#pragma unroll
        for (int j = 0; j < 4; j++) {
            wmma::fragment<wmma::matrix_b, 16, 16, 8, wmma::precision::tf32, wmma::row_major> b;
            wmma::load_matrix_sync(b, &sm[OFF_W + kk * 128 + chalf * 64 + j * 16], 128);
#pragma unroll
            for (int i = 0; i < b.num_elements; i++) b.x[i] = wmma::__float_to_tf32(b.x[i]);
            wmma::mma_sync(c[j], a, b, c[j]);
        }
    }

    __syncthreads();   // X/W regions now dead -> reuse as per-warp staging

    float* stage = &sm[warp * 16 * XS];   // 16 rows x 72 stride, 8 warps <= 9216 floats
#pragma unroll
    for (int j = 0; j < 4; j++)
        wmma::store_matrix_sync(stage + j * 16, c[j], XS, wmma::mem_row_major);
    __syncwarp();

    // write out: lane -> row r = lane>>1, 32 channels at (lane&1)*32
    int lane = tid & 31;
    int r = lane >> 1, cc = (lane & 1) * 32;
    int gn = base + strip * 16 + r;
    if (gn < N) {
        const float* row = stage + r * XS + cc;
        if (chalf == 0) {
#pragma unroll
            for (int q = 0; q < 4; q++) {
                uint4 ov;
                ov.x = bf2pair(row[q * 8 + 0], row[q * 8 + 1]);
                ov.y = bf2pair(row[q * 8 + 2], row[q * 8 + 3]);
                ov.z = bf2pair(row[q * 8 + 4], row[q * 8 + 5]);
                ov.w = bf2pair(row[q * 8 + 6], row[q * 8 + 7]);
                *(uint4*)(t + gn * 64 + cc + q * 8) = ov;
            }
        } else {
#pragma unroll
            for (int q = 0; q < 8; q++) {
                float4 ov;
                ov.x = row[q * 4 + 0] + sm[OFF_B + cc + q * 4 + 0];
                ov.y = row[q * 4 + 1] + sm[OFF_B + cc + q * 4 + 1];
                ov.z = row[q * 4 + 2] + sm[OFF_B + cc + q * 4 + 2];
                ov.w = row[q * 4 + 3] + sm[OFF_B + cc + q * 4 + 3];
                *(float4*)(pre + gn * 64 + cc + q * 4) = ov;
            }
        }
    }
}

// ---------------------------------------------------------------------------
// CSR pull (R8-proven 8-wide batching), warp per node, lane owns 2 channels.
//   s = pre[n] + EA[n]@We + sum_{src in in(n)} t[src]   (t is bf16x2)
// ---------------------------------------------------------------------------
template<bool FINAL>
__global__ void k_pull(const int* __restrict__ off, const int* __restrict__ csr,
                       const __nv_bfloat16* __restrict__ t, const float* __restrict__ pre,
                       const float* __restrict__ EA, const float* __restrict__ We,
                       float* __restrict__ hout, const int* __restrict__ batch,
                       const float* __restrict__ Wout, const float* __restrict__ bout,
                       float* __restrict__ sc, int N) {
    __shared__ float Wes[768];
    int tid = threadIdx.x;
    for (int i = tid; i < 768; i += 256) Wes[i] = We[i];
    __syncthreads();

    int node = (blockIdx.x * 256 + tid) >> 5;
    int lane = tid & 31;
    if (node >= N) return;
    int s = off[node], e = off[node + 1];
    const __nv_bfloat162* t2 = (const __nv_bfloat162*)t;
    float2 p = ((const float2*)pre)[node * 32 + lane];
    float ax = p.x, ay = p.y;

    float eav = (lane < 12) ? EA[node * 12 + lane] : 0.0f;
    const float2* We2 = (const float2*)Wes;
#pragma unroll
    for (int k = 0; k < 12; k++) {
        float a = __shfl_sync(0xffffffffu, eav, k);
        float2 w = We2[k * 32 + lane];
        ax += a * w.x; ay += a * w.y;
    }

    for (int j = s; j < e; j += 32) {
        int cnt = min(32, e - j);
        int sv = (j + lane < e) ? csr[j + lane] : 0;
        int i = 0;
#pragma unroll 1
        for (; i + 8 <= cnt; i += 8) {
            int b0 = __shfl_sync(0xffffffffu, sv, i + 0);
            int b1 = __shfl_sync(0xffffffffu, sv, i + 1);
            int b2 = __shfl_sync(0xffffffffu, sv, i + 2);
            int b3 = __shfl_sync(0xffffffffu, sv, i + 3);
            int b4 = __shfl_sync(0xffffffffu, sv, i + 4);
            int b5 = __shfl_sync(0xffffffffu, sv, i + 5);
            int b6 = __shfl_sync(0xffffffffu, sv, i + 6);
            int b7 = __shfl_sync(0xffffffffu, sv, i + 7);
            float2 v0 = __bfloat1622float2(t2[b0 * 32 + lane]);
            float2 v1 = __bfloat1622float2(t2[b1 * 32 + lane]);
            float2 v2 = __bfloat1622float2(t2[b2 * 32 + lane]);
            float2 v3 = __bfloat1622float2(t2[b3 * 32 + lane]);
            float2 v4 = __bfloat1622float2(t2[b4 * 32 + lane]);
            float2 v5 = __bfloat1622float2(t2[b5 * 32 + lane]);
            float2 v6 = __bfloat1622float2(t2[b6 * 32 + lane]);
            float2 v7 = __bfloat1622float2(t2[b7 * 32 + lane]);
            ax += ((v0.x + v1.x) + (v2.x + v3.x)) + ((v4.x + v5.x) + (v6.x + v7.x));
            ay += ((v0.y + v1.y) + (v2.y + v3.y)) + ((v4.y + v5.y) + (v6.y + v7.y));
        }
#pragma unroll 1
        for (; i < cnt; i++) {
            int b = __shfl_sync(0xffffffffu, sv, i);
            float2 v = __bfloat1622float2(t2[b * 32 + lane]);
            ax += v.x; ay += v.y;
        }
    }

    float h0 = lrelu(ax), h1 = lrelu(ay);
    if (!FINAL) {
        ((float2*)hout)[node * 32 + lane] = make_float2(h0, h1);
    } else {
        float p2 = h0 * __ldg(&Wout[2 * lane]) + h1 * __ldg(&Wout[2 * lane + 1]);
#pragma unroll
        for (int o = 16; o > 0; o >>= 1) p2 += __shfl_down_sync(0xffffffffu, p2, o);
        if (lane == 0) {
            int b = batch[node];
            atomicAdd(&sc[b], p2 + bout[0]);
            atomicAdd(&sc[NGRAPH + b], 1.0f);
        }
    }
}

// ---------------------------------------------------------------------------
// Final: out = sums/max(counts,1); restore zero-invariant on EA/sc.
// ---------------------------------------------------------------------------
__global__ void k_final(float* __restrict__ sc, float* __restrict__ out,
                        float* __restrict__ EA, int G, int N) {
    int gid = blockIdx.x * 256 + threadIdx.x;
    int tot4 = (N * 12) >> 2;
    if (gid < tot4) ((float4*)EA)[gid] = make_float4(0.f, 0.f, 0.f, 0.f);
    if (blockIdx.x == 0 && threadIdx.x < G) {
        float sv = sc[threadIdx.x], cv = sc[NGRAPH + threadIdx.x];
        out[threadIdx.x] = sv / fmaxf(cv, 1.0f);
        sc[threadIdx.x] = 0.0f;
        sc[NGRAPH + threadIdx.x] = 0.0f;
    }
}

// ---------------------------------------------------------------------------
extern "C" void kernel_launch(void* const* d_in, const int* in_sizes, int n_in,
                              void* d_out, int out_size) {
    const float* state     = (const float*)d_in[0];
    const float* action    = (const float*)d_in[1];
    const int*   edge_idx  = (const int*)d_in[2];
    const float* edge_attr = (const float*)d_in[3];
    const int*   batch     = (const int*)d_in[4];
    const float* W_in      = (const float*)d_in[5];
    const float* b_in      = (const float*)d_in[6];
    const float* W_self    = (const float*)d_in[7];
    const float* W_nbr     = (const float*)d_in[8];
    const float* W_edge    = (const float*)d_in[9];
    const float* b_conv    = (const float*)d_in[10];
    const float* W_out     = (const float*)d_in[11];
    const float* b_out     = (const float*)d_in[12];
    float* out = (float*)d_out;

    const int N = in_sizes[0] / 8;
    const int E = in_sizes[3] / 12;
    const int G = out_size;

    float *h_p, *pre_p, *ea_p, *sc_p;
    __nv_bfloat16* t_p;
    int *deg_p, *off_p, *cur_p, *csr_p, *bsum_p;
    cudaGetSymbolAddress((void**)&h_p,    g_h);
    cudaGetSymbolAddress((void**)&t_p,    g_t);
    cudaGetSymbolAddress((void**)&pre_p,  g_pre);
    cudaGetSymbolAddress((void**)&ea_p,   g_EA);
    cudaGetSymbolAddress((void**)&deg_p,  g_deg);
    cudaGetSymbolAddress((void**)&off_p,  g_off);
    cudaGetSymbolAddress((void**)&cur_p,  g_cur);
    cudaGetSymbolAddress((void**)&csr_p,  g_csr);
    cudaGetSymbolAddress((void**)&bsum_p, g_bsum);
    cudaGetSymbolAddress((void**)&sc_p,   g_sc);

    const int smemBytes = SMEM_FLOATS * 4;
    cudaFuncSetAttribute(k_gemm<true>,  cudaFuncAttributeMaxDynamicSharedMemorySize, smemBytes);
    cudaFuncSetAttribute(k_gemm<false>, cudaFuncAttributeMaxDynamicSharedMemorySize, smemBytes);

    static cudaStream_t sA = nullptr;
    static cudaEvent_t evRoot = nullptr, evCsr = nullptr;
    if (!sA) {
        cudaStreamCreateWithFlags(&sA, cudaStreamNonBlocking);
        cudaEventCreateWithFlags(&evRoot, cudaEventDisableTiming);
        cudaEventCreateWithFlags(&evCsr,  cudaEventDisableTiming);
    }

    const int pullBlocks = (N + 7) / 8;
    const int gemmBlocks = (N + 63) / 64;
    const int edgeBlocks = (E + 255) / 256;
    const int scanBlocks = (N + SCAN_CHUNK - 1) / SCAN_CHUNK;
    const int finBlocks  = ((N * 12) / 4 + 255) / 256;

    // fork: CSR/EA chain on side stream
    cudaEventRecord(evRoot, 0);
    cudaStreamWaitEvent(sA, evRoot, 0);
    k_edge<<<edgeBlocks, 256, 0, sA>>>(edge_idx, edge_attr, deg_p, ea_p, E);
    k_scan1<<<scanBlocks, 256, 0, sA>>>(deg_p, bsum_p, N);
    k_scan2<<<scanBlocks, 256, 0, sA>>>(deg_p, bsum_p, off_p, cur_p, N, E);
    k_fill<<<edgeBlocks, 256, 0, sA>>>(edge_idx, cur_p, csr_p, E);
    cudaEventRecord(evCsr, sA);

    // main chain: gemm0 starts immediately (no edge dependency)
    k_gemm<true><<<gemmBlocks, 256, smemBytes>>>(state, action, W_in, b_in,
                                                 nullptr, W_nbr, W_self, b_conv,
                                                 t_p, pre_p, N);
    cudaStreamWaitEvent(0, evCsr, 0);
    k_pull<false><<<pullBlocks, 256>>>(off_p, csr_p, t_p, pre_p, ea_p, W_edge,
                                       h_p, nullptr, nullptr, nullptr, nullptr, N);
    k_gemm<false><<<gemmBlocks, 256, smemBytes>>>(nullptr, nullptr, nullptr, nullptr,
                                                  h_p, W_nbr + 4096, W_self + 4096,
                                                  b_conv + 64, t_p, pre_p, N);
    k_pull<true><<<pullBlocks, 256>>>(off_p, csr_p, t_p, pre_p, ea_p, W_edge + 768,
                                      nullptr, batch, W_out, b_out, sc_p, N);
    k_final<<<finBlocks, 256>>>(sc_p, out, ea_p, G, N);
}